// round 13
// baseline (speedup 1.0000x reference)
#include <cuda_runtime.h>
#include <cuda_fp16.h>
#include <cstdint>

#define HID   512
#define DHID  2048
#define NBAT  32
#define NSEQ  2048
#define NROWS (NSEQ*NBAT)   // 65536

#define TM    256           // rows per CTA
#define KC    64            // k-chunk width (halfs)
#define NCH   128           // n-chunk width
#define LDT   144           // smem row stride bytes (72 halfs) -> conflict-free ldmatrix

#define A_STAGE (256*LDT)   // 36864
#define B_STAGE (128*LDT)   // 18432

// ---- SMEM layout (bytes): 3-stage A + 3-stage B ----
#define B_BASE  (3*A_STAGE)           // 110592
#define VS_OFF  (B_BASE + 3*B_STAGE)  // 165888 (512 floats)
#define RS_OFF  (VS_OFF + 2048)       // 167936 (256 floats)
#define SMEM_TOTAL (RS_OFF + 1024)    // 168960

// ---- heterogeneous prep grid: small jobs FIRST so they overlap convA ----
#define HP_BLKS    128
#define CONVW_BLKS 128
#define CONVA_BLKS 8192
#define PREP_BLKS  (HP_BLKS + CONVW_BLKS + CONVA_BLKS)

__device__ float  g_hp[NBAT*HID];
__device__ __half g_We[HID*HID];               // W_e transposed: [n][k] fp16
__device__ __half g_enc16[(size_t)NROWS*HID];  // enc fp16, row-major [row][k]
__device__ float  g_logT[NBAT*NSEQ];           // logits transposed: [b][s]

#define LDSM4(R0,R1,R2,R3,ADDR) \
  asm volatile("ldmatrix.sync.aligned.m8n8.x4.shared.b16 {%0,%1,%2,%3}, [%4];" \
    : "=r"(R0),"=r"(R1),"=r"(R2),"=r"(R3) : "r"(ADDR))

#define MMA16816(C0,C1,C2,C3,A0,A1,A2,A3,B0,B1) \
  asm volatile("mma.sync.aligned.m16n8k16.row.col.f32.f16.f16.f32 " \
    "{%0,%1,%2,%3},{%4,%5,%6,%7},{%8,%9},{%0,%1,%2,%3};" \
    : "+f"(C0),"+f"(C1),"+f"(C2),"+f"(C3) \
    : "r"(A0),"r"(A1),"r"(A2),"r"(A3),"r"(B0),"r"(B1))

#define CP16(DST, SRC) \
  asm volatile("cp.async.cg.shared.global [%0], [%1], 16;" :: "r"(DST), "l"(SRC) : "memory")
#define CP_COMMIT() asm volatile("cp.async.commit_group;" ::: "memory")
#define CP_WAIT1()  asm volatile("cp.async.wait_group 1;" ::: "memory")
#define CP_WAIT0()  asm volatile("cp.async.wait_group 0;" ::: "memory")

__device__ __forceinline__ uint32_t smem_u32(const void* p) {
    uint32_t a;
    asm("{ .reg .u64 t; cvta.to.shared.u64 t, %1; cvt.u32.u64 %0, t; }" : "=r"(a) : "l"(p));
    return a;
}
__device__ __forceinline__ float tanh_approx(float x) {
    float y;
    asm("tanh.approx.f32 %0, %1;" : "=f"(y) : "f"(x));
    return y;
}

// ---------------------------------------------------------------------------
// k_initHP: g_hp[b][d] = b_attn[d]   (must precede k_prep's hpart atomics)
// ---------------------------------------------------------------------------
__global__ void k_initHP(const float* __restrict__ b_attn)
{
    g_hp[blockIdx.x*HID + threadIdx.x] = b_attn[threadIdx.x];
}

// ---------------------------------------------------------------------------
// k_prep: heterogeneous grid, 256 threads/block (unchanged from v4r).
// ---------------------------------------------------------------------------
__global__ void __launch_bounds__(256)
k_prep(const float* __restrict__ enc, const float* __restrict__ W,
       const float* __restrict__ hidden)
{
    __shared__ float sh[64*33];
    const int p = blockIdx.x;
    const int tid = threadIdx.x;

    if (p < HP_BLKS) {
        // ---------------- hpart: 16 ks x 2 dg x 4 bg ----------------
        const int ks = p & 15;
        const int dg = (p >> 4) & 1;
        const int bg = p >> 5;
        const int d  = dg*256 + tid;
        const int k0 = ks*128;
        const int b0 = bg*8;

        #pragma unroll
        for (int i = tid; i < 8*128; i += 256) {
            int b = i >> 7, kk = i & 127;
            sh[b*128 + kk] = hidden[(size_t)(b0 + b)*DHID + k0 + kk];
        }
        __syncthreads();

        float acc[8];
        #pragma unroll
        for (int b = 0; b < 8; b++) acc[b] = 0.f;

        #pragma unroll 4
        for (int kk = 0; kk < 128; kk++) {
            float w = W[(size_t)(k0 + kk)*HID + d];
            #pragma unroll
            for (int b = 0; b < 8; b++) acc[b] = fmaf(sh[b*128 + kk], w, acc[b]);
        }
        #pragma unroll
        for (int b = 0; b < 8; b++) atomicAdd(&g_hp[(b0 + b)*HID + d], acc[b]);
    }
    else if (p < HP_BLKS + CONVW_BLKS) {
        // ---------------- convW: 8 kc x 16 nb ----------------
        const int q  = p - HP_BLKS;
        const int kc = q & 7;
        const int n0 = (q >> 3) * 32;
        const int tx = tid & 31, ty = tid >> 5;
        #pragma unroll
        for (int i = 0; i < 8; i++) {
            int r = ty + i * 8;
            sh[r*33 + tx] = W[(size_t)(DHID + kc*64 + r)*HID + n0 + tx];
        }
        __syncthreads();
        int nl = tid >> 3;
        int g  = tid & 7;
        int n  = n0 + nl;
        __half2 h0 = __floats2half2_rn(sh[(g*8+0)*33 + nl], sh[(g*8+1)*33 + nl]);
        __half2 h1 = __floats2half2_rn(sh[(g*8+2)*33 + nl], sh[(g*8+3)*33 + nl]);
        __half2 h2 = __floats2half2_rn(sh[(g*8+4)*33 + nl], sh[(g*8+5)*33 + nl]);
        __half2 h3 = __floats2half2_rn(sh[(g*8+6)*33 + nl], sh[(g*8+7)*33 + nl]);
        uint4 val;
        val.x = *(uint32_t*)&h0; val.y = *(uint32_t*)&h1;
        val.z = *(uint32_t*)&h2; val.w = *(uint32_t*)&h3;
        *(uint4*)(g_We + (size_t)n*HID + kc*64 + g*8) = val;
    }
    else {
        // ---------------- convA ----------------
        const int q = p - (HP_BLKS + CONVW_BLKS);
        const float4* src = (const float4*)enc;
        size_t base = (size_t)q * 1024 + tid;
        #pragma unroll
        for (int i = 0; i < 4; i++) {
            size_t idx = base + (size_t)i * 256;
            float4 f = src[idx];
            __half2 h0 = __floats2half2_rn(f.x, f.y);
            __half2 h1 = __floats2half2_rn(f.z, f.w);
            uint2 val;
            val.x = *(uint32_t*)&h0; val.y = *(uint32_t*)&h1;
            *(uint2*)(g_enc16 + idx*4) = val;
        }
    }
}

// ---------------------------------------------------------------------------
// k_main v5: CTA tile 256x128, warp tile 64x64 (8 warps, 4M x 2N).
// 3-stage cp.async pipeline, one __syncthreads per chunk, 1 CTA/SM.
// 32 chunks gi = nc*8 + kc; epilogue at kc==7.
// Arithmetic intensity: 4KB LDSM -> 32 MMA (128 KFLOP) per warp per k16.
// ---------------------------------------------------------------------------
__device__ __forceinline__ void prefetch_chunk(uint32_t abuf, uint32_t bbuf,
                                               const __half* __restrict__ encrow,
                                               int nc, int kc, int tid)
{
    #pragma unroll
    for (int i = 0; i < 8; i++) {
        int idx = tid + i*256;               // 0..2047
        int m   = idx >> 3, seg = idx & 7;
        CP16(abuf + m*LDT + seg*16, encrow + (size_t)m*HID + kc*KC + seg*8);
    }
    #pragma unroll
    for (int i = 0; i < 4; i++) {
        int idx = tid + i*256;               // 0..1023
        int n   = idx >> 3, seg = idx & 7;
        CP16(bbuf + n*LDT + seg*16, g_We + (size_t)(nc*NCH + n)*HID + kc*KC + seg*8);
    }
    CP_COMMIT();
}

__global__ void __launch_bounds__(256, 1)
k_main(const float* __restrict__ v)
{
    extern __shared__ char sm[];
    const uint32_t smem_base = smem_u32(sm);
    const int tid  = threadIdx.x;
    const int warp = tid >> 5, lane = tid & 31;
    const int wm   = warp >> 1, wn = warp & 1;
    const int g    = lane >> 2, t = lane & 3;
    const int tile0 = blockIdx.x * TM;

    float* vs = (float*)(sm + VS_OFF);
    float* rowsum = (float*)(sm + RS_OFF);

    vs[tid] = v[tid];
    vs[tid + 256] = v[tid + 256];
    rowsum[tid] = 0.f;

    const __half* encrow = g_enc16 + (size_t)tile0 * HID;

    // lane-dependent ldmatrix offsets
    const uint32_t arow_off = (uint32_t)(lane & 15)*LDT + ((uint32_t)lane >> 4)*16
                            + (uint32_t)wm*64*LDT;
    const uint32_t brow_off = ((uint32_t)(lane & 7) + (((uint32_t)lane >> 4) << 3))*LDT
                            + ((((uint32_t)lane >> 3) & 1) << 4)
                            + (uint32_t)wn*64*LDT;

    float acc[4][8][4];
    #pragma unroll
    for (int mt = 0; mt < 4; mt++)
        #pragma unroll
        for (int nt = 0; nt < 8; nt++)
            #pragma unroll
            for (int j = 0; j < 4; j++) acc[mt][nt][j] = 0.f;

    prefetch_chunk(smem_base + 0*A_STAGE, smem_base + B_BASE + 0*B_STAGE,
                   encrow, 0, 0, tid);
    prefetch_chunk(smem_base + 1*A_STAGE, smem_base + B_BASE + 1*B_STAGE,
                   encrow, 0, 1, tid);

    int s = 0, sp = 2;      // compute buffer, prefetch buffer (gi+2)%3
    #pragma unroll 1
    for (int gi = 0; gi < 32; gi++) {
        if (gi == 31) { CP_WAIT0(); } else { CP_WAIT1(); }
        __syncthreads();

        if (gi + 2 < 32) {
            const int gi2 = gi + 2;
            prefetch_chunk(smem_base + sp*A_STAGE,
                           smem_base + B_BASE + sp*B_STAGE,
                           encrow, gi2 >> 3, gi2 & 7, tid);
        }

        const uint32_t Ab = smem_base + s*A_STAGE + arow_off;
        const uint32_t Bb = smem_base + B_BASE + s*B_STAGE + brow_off;

        #pragma unroll
        for (int ks = 0; ks < 4; ks++) {
            uint32_t A[4][4], B[4][4];
            #pragma unroll
            for (int mt = 0; mt < 4; mt++)
                LDSM4(A[mt][0], A[mt][1], A[mt][2], A[mt][3], Ab + mt*16*LDT + ks*32);
            #pragma unroll
            for (int p = 0; p < 4; p++)
                LDSM4(B[p][0], B[p][1], B[p][2], B[p][3], Bb + p*16*LDT + ks*32);
            #pragma unroll
            for (int mt = 0; mt < 4; mt++) {
                #pragma unroll
                for (int nt = 0; nt < 8; nt++) {
                    const int p = nt >> 1, h = (nt & 1) << 1;
                    MMA16816(acc[mt][nt][0], acc[mt][nt][1], acc[mt][nt][2], acc[mt][nt][3],
                             A[mt][0], A[mt][1], A[mt][2], A[mt][3],
                             B[p][h], B[p][h+1]);
                }
            }
        }

        if ((gi & 7) == 7) {
            // ---- epilogue for n-chunk nc = gi>>3 ----
            const int nc = gi >> 3;
            #pragma unroll
            for (int mt = 0; mt < 4; mt++) {
                #pragma unroll
                for (int rh = 0; rh < 2; rh++) {
                    const int row = wm*64 + mt*16 + rh*8 + g;
                    const int b   = row & 31;
                    float p = 0.f;
                    #pragma unroll
                    for (int nt = 0; nt < 8; nt++) {
                        const int col = nc*NCH + wn*64 + nt*8 + t*2;
                        float2 hp2 = __ldg((const float2*)(g_hp + b*HID + col));
                        const float2 v2 = *(const float2*)(vs + col);
                        float x0 = tanh_approx(acc[mt][nt][rh*2 + 0] + hp2.x);
                        float x1 = tanh_approx(acc[mt][nt][rh*2 + 1] + hp2.y);
                        p = fmaf(x0, v2.x, p);
                        p = fmaf(x1, v2.y, p);
                        acc[mt][nt][rh*2 + 0] = 0.f;
                        acc[mt][nt][rh*2 + 1] = 0.f;
                    }
                    p += __shfl_xor_sync(0xffffffffu, p, 1);
                    p += __shfl_xor_sync(0xffffffffu, p, 2);
                    if (t == 0) atomicAdd(&rowsum[row], p);
                }
            }
        }

        s  = (s  == 2) ? 0 : s  + 1;
        sp = (sp == 2) ? 0 : sp + 1;
    }

    __syncthreads();
    {
        const int r = tile0 + tid;
        g_logT[(r & 31)*NSEQ + (r >> 5)] = rowsum[tid];
    }
}

// ---------------------------------------------------------------------------
// k_softmax: per batch b, softmax over s of g_logT[b][s] -> out[b][s]
// ---------------------------------------------------------------------------
__global__ void k_softmax(float* __restrict__ out)
{
    __shared__ float red[8];
    int b = blockIdx.x, tid = threadIdx.x;
    int warp = tid >> 5, lane = tid & 31;

    float x[8];
    #pragma unroll
    for (int j = 0; j < 8; j++) x[j] = g_logT[b*NSEQ + j*256 + tid];

    float m = x[0];
    #pragma unroll
    for (int j = 1; j < 8; j++) m = fmaxf(m, x[j]);
    #pragma unroll
    for (int o = 16; o; o >>= 1) m = fmaxf(m, __shfl_xor_sync(0xffffffffu, m, o));
    if (lane == 0) red[warp] = m;
    __syncthreads();
    #pragma unroll
    for (int w = 0; w < 8; w++) m = fmaxf(m, red[w]);
    __syncthreads();

    float e[8]; float s = 0.f;
    #pragma unroll
    for (int j = 0; j < 8; j++) { e[j] = expf(x[j] - m); s += e[j]; }
    #pragma unroll
    for (int o = 16; o; o >>= 1) s += __shfl_xor_sync(0xffffffffu, s, o);
    if (lane == 0) red[warp] = s;
    __syncthreads();
    s = 0.f;
    #pragma unroll
    for (int w = 0; w < 8; w++) s += red[w];

    float inv = 1.f / s;
    #pragma unroll
    for (int j = 0; j < 8; j++) out[b*NSEQ + j*256 + tid] = e[j] * inv;
}

// ---------------------------------------------------------------------------
extern "C" void kernel_launch(void* const* d_in, const int* in_sizes, int n_in,
                              void* d_out, int out_size)
{
    const float* hidden = (const float*)d_in[0];   // (32, 2048)
    const float* enc    = (const float*)d_in[1];   // (2048, 32, 512)
    const float* W      = (const float*)d_in[2];   // (2560, 512)
    const float* b_attn = (const float*)d_in[3];   // (512,)
    const float* v      = (const float*)d_in[4];   // (512,)
    float* out = (float*)d_out;                    // (32, 2048)

    cudaFuncSetAttribute(k_main, cudaFuncAttributeMaxDynamicSharedMemorySize, SMEM_TOTAL);

    k_initHP <<<32, 512>>>(b_attn);
    k_prep   <<<PREP_BLKS, 256>>>(enc, W, hidden);
    k_main   <<<NROWS/TM, 256, SMEM_TOTAL>>>(v);
    k_softmax<<<NBAT, 256>>>(out);
}

// round 16
// speedup vs baseline: 1.0014x; 1.0014x over previous
#include <cuda_runtime.h>
#include <cuda_fp16.h>
#include <cstdint>

#define HID   512
#define DHID  2048
#define NBAT  32
#define NSEQ  2048
#define NROWS (NSEQ*NBAT)   // 65536

#define TM    128           // rows per CTA
#define KC    64            // k-chunk width (halfs)
#define NCH   256           // n-chunk (accumulator) width
#define LDT   144           // smem row stride bytes (72 halfs) -> conflict-free ldmatrix

#define A_STAGE (128*LDT)   // 18432
#define B_STAGE (256*LDT)   // 36864
#define STAGE   (A_STAGE + B_STAGE)   // 55296

// ---- SMEM layout (bytes): 3 stages of (A | B) ----
#define VS_OFF  (3*STAGE)             // 165888 (512 floats)
#define RS_OFF  (VS_OFF + 2048)       // 167936 (128 floats)
#define SMEM_TOTAL (RS_OFF + 512)     // 168448

// ---- heterogeneous prep grid: small jobs FIRST so they overlap convA ----
#define HP_BLKS    128
#define CONVW_BLKS 128
#define CONVA_BLKS 8192
#define PREP_BLKS  (HP_BLKS + CONVW_BLKS + CONVA_BLKS)

__device__ float  g_hp[NBAT*HID];
__device__ __half g_We[HID*HID];               // W_e transposed: [n][k] fp16
__device__ __half g_enc16[(size_t)NROWS*HID];  // enc fp16, row-major [row][k]
__device__ float  g_logT[NBAT*NSEQ];           // logits transposed: [b][s]

#define LDSM4(R0,R1,R2,R3,ADDR) \
  asm volatile("ldmatrix.sync.aligned.m8n8.x4.shared.b16 {%0,%1,%2,%3}, [%4];" \
    : "=r"(R0),"=r"(R1),"=r"(R2),"=r"(R3) : "r"(ADDR))

#define MMA16816(C0,C1,C2,C3,A0,A1,A2,A3,B0,B1) \
  asm volatile("mma.sync.aligned.m16n8k16.row.col.f32.f16.f16.f32 " \
    "{%0,%1,%2,%3},{%4,%5,%6,%7},{%8,%9},{%0,%1,%2,%3};" \
    : "+f"(C0),"+f"(C1),"+f"(C2),"+f"(C3) \
    : "r"(A0),"r"(A1),"r"(A2),"r"(A3),"r"(B0),"r"(B1))

#define CP16(DST, SRC) \
  asm volatile("cp.async.cg.shared.global [%0], [%1], 16;" :: "r"(DST), "l"(SRC) : "memory")
#define CP_COMMIT() asm volatile("cp.async.commit_group;" ::: "memory")
#define CP_WAIT1()  asm volatile("cp.async.wait_group 1;" ::: "memory")
#define CP_WAIT0()  asm volatile("cp.async.wait_group 0;" ::: "memory")

__device__ __forceinline__ uint32_t smem_u32(const void* p) {
    uint32_t a;
    asm("{ .reg .u64 t; cvta.to.shared.u64 t, %1; cvt.u32.u64 %0, t; }" : "=r"(a) : "l"(p));
    return a;
}
__device__ __forceinline__ float tanh_approx(float x) {
    float y;
    asm("tanh.approx.f32 %0, %1;" : "=f"(y) : "f"(x));
    return y;
}

// ---------------------------------------------------------------------------
// k_initHP: g_hp[b][d] = b_attn[d]   (must precede k_prep's hpart atomics)
// ---------------------------------------------------------------------------
__global__ void k_initHP(const float* __restrict__ b_attn)
{
    g_hp[blockIdx.x*HID + threadIdx.x] = b_attn[threadIdx.x];
}

// ---------------------------------------------------------------------------
// k_prep: heterogeneous grid, 256 threads/block (unchanged — proven in R12).
// ---------------------------------------------------------------------------
__global__ void __launch_bounds__(256)
k_prep(const float* __restrict__ enc, const float* __restrict__ W,
       const float* __restrict__ hidden)
{
    __shared__ float sh[64*33];
    const int p = blockIdx.x;
    const int tid = threadIdx.x;

    if (p < HP_BLKS) {
        // ---------------- hpart: 16 ks x 2 dg x 4 bg ----------------
        const int ks = p & 15;
        const int dg = (p >> 4) & 1;
        const int bg = p >> 5;
        const int d  = dg*256 + tid;
        const int k0 = ks*128;
        const int b0 = bg*8;

        #pragma unroll
        for (int i = tid; i < 8*128; i += 256) {
            int b = i >> 7, kk = i & 127;
            sh[b*128 + kk] = hidden[(size_t)(b0 + b)*DHID + k0 + kk];
        }
        __syncthreads();

        float acc[8];
        #pragma unroll
        for (int b = 0; b < 8; b++) acc[b] = 0.f;

        #pragma unroll 4
        for (int kk = 0; kk < 128; kk++) {
            float w = W[(size_t)(k0 + kk)*HID + d];
            #pragma unroll
            for (int b = 0; b < 8; b++) acc[b] = fmaf(sh[b*128 + kk], w, acc[b]);
        }
        #pragma unroll
        for (int b = 0; b < 8; b++) atomicAdd(&g_hp[(b0 + b)*HID + d], acc[b]);
    }
    else if (p < HP_BLKS + CONVW_BLKS) {
        // ---------------- convW: 8 kc x 16 nb ----------------
        const int q  = p - HP_BLKS;
        const int kc = q & 7;
        const int n0 = (q >> 3) * 32;
        const int tx = tid & 31, ty = tid >> 5;
        #pragma unroll
        for (int i = 0; i < 8; i++) {
            int r = ty + i * 8;
            sh[r*33 + tx] = W[(size_t)(DHID + kc*64 + r)*HID + n0 + tx];
        }
        __syncthreads();
        int nl = tid >> 3;
        int g  = tid & 7;
        int n  = n0 + nl;
        __half2 h0 = __floats2half2_rn(sh[(g*8+0)*33 + nl], sh[(g*8+1)*33 + nl]);
        __half2 h1 = __floats2half2_rn(sh[(g*8+2)*33 + nl], sh[(g*8+3)*33 + nl]);
        __half2 h2 = __floats2half2_rn(sh[(g*8+4)*33 + nl], sh[(g*8+5)*33 + nl]);
        __half2 h3 = __floats2half2_rn(sh[(g*8+6)*33 + nl], sh[(g*8+7)*33 + nl]);
        uint4 val;
        val.x = *(uint32_t*)&h0; val.y = *(uint32_t*)&h1;
        val.z = *(uint32_t*)&h2; val.w = *(uint32_t*)&h3;
        *(uint4*)(g_We + (size_t)n*HID + kc*64 + g*8) = val;
    }
    else {
        // ---------------- convA ----------------
        const int q = p - (HP_BLKS + CONVW_BLKS);
        const float4* src = (const float4*)enc;
        size_t base = (size_t)q * 1024 + tid;
        #pragma unroll
        for (int i = 0; i < 4; i++) {
            size_t idx = base + (size_t)i * 256;
            float4 f = src[idx];
            __half2 h0 = __floats2half2_rn(f.x, f.y);
            __half2 h1 = __floats2half2_rn(f.z, f.w);
            uint2 val;
            val.x = *(uint32_t*)&h0; val.y = *(uint32_t*)&h1;
            *(uint2*)(g_enc16 + idx*4) = val;
        }
    }
}

// ---------------------------------------------------------------------------
// k_main v6: 512 threads, 16 warps (2M x 8N), warp tile 64x32, 1 CTA/SM.
// CTA acc tile 128 x 256 -> only 2 n-chunks (A re-read halved vs v4r),
// 16 chunks total (half the barriers), 3-stage cp.async pipeline.
// ---------------------------------------------------------------------------
__device__ __forceinline__ void prefetch_chunk(uint32_t abuf, uint32_t bbuf,
                                               const __half* __restrict__ encrow,
                                               int nc, int kc, int tid)
{
    #pragma unroll
    for (int i = 0; i < 2; i++) {
        int idx = tid + i*512;               // 0..1023  (128 rows x 8 segs)
        int m   = idx >> 3, seg = idx & 7;
        CP16(abuf + m*LDT + seg*16, encrow + (size_t)m*HID + kc*KC + seg*8);
    }
    #pragma unroll
    for (int i = 0; i < 4; i++) {
        int idx = tid + i*512;               // 0..2047  (256 rows x 8 segs)
        int n   = idx >> 3, seg = idx & 7;
        CP16(bbuf + n*LDT + seg*16, g_We + (size_t)(nc*NCH + n)*HID + kc*KC + seg*8);
    }
    CP_COMMIT();
}

__global__ void __launch_bounds__(512, 1)
k_main(const float* __restrict__ v)
{
    extern __shared__ char sm[];
    const uint32_t smem_base = smem_u32(sm);
    const int tid  = threadIdx.x;
    const int warp = tid >> 5, lane = tid & 31;
    const int wm   = warp >> 3, wn = warp & 7;   // 2M x 8N
    const int g    = lane >> 2, t = lane & 3;
    const int tile0 = blockIdx.x * TM;

    float* vs = (float*)(sm + VS_OFF);
    float* rowsum = (float*)(sm + RS_OFF);

    vs[tid] = v[tid];
    if (tid < TM) rowsum[tid] = 0.f;

    const __half* encrow = g_enc16 + (size_t)tile0 * HID;

    // lane-dependent ldmatrix offsets
    const uint32_t arow_off = (uint32_t)(lane & 15)*LDT + ((uint32_t)lane >> 4)*16
                            + (uint32_t)wm*64*LDT;
    const uint32_t brow_off = ((uint32_t)(lane & 7) + (((uint32_t)lane >> 4) << 3))*LDT
                            + ((((uint32_t)lane >> 3) & 1) << 4)
                            + (uint32_t)wn*32*LDT;

    float acc[4][4][4];
    #pragma unroll
    for (int mt = 0; mt < 4; mt++)
        #pragma unroll
        for (int nt = 0; nt < 4; nt++)
            #pragma unroll
            for (int j = 0; j < 4; j++) acc[mt][nt][j] = 0.f;

    prefetch_chunk(smem_base + 0*STAGE, smem_base + 0*STAGE + A_STAGE,
                   encrow, 0, 0, tid);
    prefetch_chunk(smem_base + 1*STAGE, smem_base + 1*STAGE + A_STAGE,
                   encrow, 0, 1, tid);

    int s = 0, sp = 2;      // compute buffer, prefetch buffer (gi+2)%3
    #pragma unroll 1
    for (int gi = 0; gi < 16; gi++) {
        if (gi == 15) { CP_WAIT0(); } else { CP_WAIT1(); }
        __syncthreads();

        if (gi + 2 < 16) {
            const int gi2 = gi + 2;
            prefetch_chunk(smem_base + sp*STAGE,
                           smem_base + sp*STAGE + A_STAGE,
                           encrow, gi2 >> 3, gi2 & 7, tid);
        }

        const uint32_t Ab = smem_base + s*STAGE + arow_off;
        const uint32_t Bb = smem_base + s*STAGE + A_STAGE + brow_off;

        #pragma unroll
        for (int ks = 0; ks < 4; ks++) {
            uint32_t A[4][4], B[2][4];
            #pragma unroll
            for (int mt = 0; mt < 4; mt++)
                LDSM4(A[mt][0], A[mt][1], A[mt][2], A[mt][3], Ab + mt*16*LDT + ks*32);
            #pragma unroll
            for (int p = 0; p < 2; p++)
                LDSM4(B[p][0], B[p][1], B[p][2], B[p][3], Bb + p*16*LDT + ks*32);
            #pragma unroll
            for (int mt = 0; mt < 4; mt++) {
                #pragma unroll
                for (int nt = 0; nt < 4; nt++) {
                    const int p = nt >> 1, h = (nt & 1) << 1;
                    MMA16816(acc[mt][nt][0], acc[mt][nt][1], acc[mt][nt][2], acc[mt][nt][3],
                             A[mt][0], A[mt][1], A[mt][2], A[mt][3],
                             B[p][h], B[p][h+1]);
                }
            }
        }

        if ((gi & 7) == 7) {
            // ---- epilogue for n-chunk nc = gi>>3 ----
            const int nc = gi >> 3;
            #pragma unroll
            for (int mt = 0; mt < 4; mt++) {
                #pragma unroll
                for (int rh = 0; rh < 2; rh++) {
                    const int row = wm*64 + mt*16 + rh*8 + g;
                    const int b   = row & 31;
                    float p = 0.f;
                    #pragma unroll
                    for (int nt = 0; nt < 4; nt++) {
                        const int col = nc*NCH + wn*32 + nt*8 + t*2;
                        float2 hp2 = __ldg((const float2*)(g_hp + b*HID + col));
                        const float2 v2 = *(const float2*)(vs + col);
                        float x0 = tanh_approx(acc[mt][nt][rh*2 + 0] + hp2.x);
                        float x1 = tanh_approx(acc[mt][nt][rh*2 + 1] + hp2.y);
                        p = fmaf(x0, v2.x, p);
                        p = fmaf(x1, v2.y, p);
                        acc[mt][nt][rh*2 + 0] = 0.f;
                        acc[mt][nt][rh*2 + 1] = 0.f;
                    }
                    p += __shfl_xor_sync(0xffffffffu, p, 1);
                    p += __shfl_xor_sync(0xffffffffu, p, 2);
                    if (t == 0) atomicAdd(&rowsum[row], p);
                }
            }
        }

        s  = (s  == 2) ? 0 : s  + 1;
        sp = (sp == 2) ? 0 : sp + 1;
    }

    __syncthreads();
    if (tid < TM) {
        const int r = tile0 + tid;
        g_logT[(r & 31)*NSEQ + (r >> 5)] = rowsum[tid];
    }
}

// ---------------------------------------------------------------------------
// k_softmax: per batch b, softmax over s of g_logT[b][s] -> out[b][s]
// ---------------------------------------------------------------------------
__global__ void k_softmax(float* __restrict__ out)
{
    __shared__ float red[8];
    int b = blockIdx.x, tid = threadIdx.x;
    int warp = tid >> 5, lane = tid & 31;

    float x[8];
    #pragma unroll
    for (int j = 0; j < 8; j++) x[j] = g_logT[b*NSEQ + j*256 + tid];

    float m = x[0];
    #pragma unroll
    for (int j = 1; j < 8; j++) m = fmaxf(m, x[j]);
    #pragma unroll
    for (int o = 16; o; o >>= 1) m = fmaxf(m, __shfl_xor_sync(0xffffffffu, m, o));
    if (lane == 0) red[warp] = m;
    __syncthreads();
    #pragma unroll
    for (int w = 0; w < 8; w++) m = fmaxf(m, red[w]);
    __syncthreads();

    float e[8]; float s = 0.f;
    #pragma unroll
    for (int j = 0; j < 8; j++) { e[j] = expf(x[j] - m); s += e[j]; }
    #pragma unroll
    for (int o = 16; o; o >>= 1) s += __shfl_xor_sync(0xffffffffu, s, o);
    if (lane == 0) red[warp] = s;
    __syncthreads();
    s = 0.f;
    #pragma unroll
    for (int w = 0; w < 8; w++) s += red[w];

    float inv = 1.f / s;
    #pragma unroll
    for (int j = 0; j < 8; j++) out[b*NSEQ + j*256 + tid] = e[j] * inv;
}

// ---------------------------------------------------------------------------
extern "C" void kernel_launch(void* const* d_in, const int* in_sizes, int n_in,
                              void* d_out, int out_size)
{
    const float* hidden = (const float*)d_in[0];   // (32, 2048)
    const float* enc    = (const float*)d_in[1];   // (2048, 32, 512)
    const float* W      = (const float*)d_in[2];   // (2560, 512)
    const float* b_attn = (const float*)d_in[3];   // (512,)
    const float* v      = (const float*)d_in[4];   // (512,)
    float* out = (float*)d_out;                    // (32, 2048)

    cudaFuncSetAttribute(k_main, cudaFuncAttributeMaxDynamicSharedMemorySize, SMEM_TOTAL);

    k_initHP <<<32, 512>>>(b_attn);
    k_prep   <<<PREP_BLKS, 256>>>(enc, W, hidden);
    k_main   <<<NROWS/TM, 512, SMEM_TOTAL>>>(v);
    k_softmax<<<NBAT, 256>>>(out);
}